// round 1
// baseline (speedup 1.0000x reference)
#include <cuda_runtime.h>
#include <math.h>

// GradientHistLoss: per-sample 95th-percentile-scaled 64-bin soft histograms,
// weighted L1 between normalized pred/gt histograms, mean over 4 samples.
//
// Quantile via 3-level radix select on float bits (valid: inputs >= 0).

#define NBINS   64
#define BATCH   4
#define NB0     2048
#define NB1     2048
#define NB2     1024

// ---- device scratch (no allocations allowed) ----
__device__ unsigned g_counts0[BATCH * 2 * NB0];
__device__ unsigned g_counts1[BATCH * 2 * NB1];
__device__ unsigned g_counts2[BATCH * 2 * NB2];
__device__ unsigned g_prefix[BATCH][2];   // accumulated high bits per (sample, rank)
__device__ unsigned g_rem[BATCH][2];      // remaining rank within current prefix
__device__ float    g_soft[BATCH][2][NBINS]; // [b][0]=pred hist, [b][1]=gt hist
__device__ float    g_invbw[BATCH];       // 64 / max_val per sample

// -------------------------------------------------------------------------
__global__ void init_kernel(unsigned k0, unsigned k1) {
    int idx = blockIdx.x * blockDim.x + threadIdx.x;
    int stride = gridDim.x * blockDim.x;
    for (int i = idx; i < BATCH * 2 * NB0; i += stride) g_counts0[i] = 0u;
    for (int i = idx; i < BATCH * 2 * NB1; i += stride) g_counts1[i] = 0u;
    for (int i = idx; i < BATCH * 2 * NB2; i += stride) g_counts2[i] = 0u;
    for (int i = idx; i < BATCH * 2 * NBINS; i += stride)
        ((float*)g_soft)[i] = 0.0f;
    if (idx < BATCH * 2) {
        int b = idx >> 1, r = idx & 1;
        g_prefix[b][r] = 0u;
        g_rem[b][r]    = r ? k1 : k0;
    }
}

// -------------------------------------------------------------------------
// One radix-select counting pass. level selects the counts array + bit field.
//   level 0: digit = key >> 21      (11 bits), match all
//   level 1: digit = (key>>10)&7FF  (11 bits), match key>>21 == prefix
//   level 2: digit = key & 3FF      (10 bits), match key>>10 == prefix
__global__ void radix_hist(const float* __restrict__ gt, int nper, int level) {
    __shared__ unsigned sh[2 * NB0];   // max size; levels use first 2*bins

    int bins, dshift, mshift; unsigned dmask; int matchAll;
    unsigned* counts;
    if (level == 0) { bins = NB0; dshift = 21; dmask = 0x7FFu; mshift = 0;  matchAll = 1; counts = g_counts0; }
    else if (level == 1) { bins = NB1; dshift = 10; dmask = 0x7FFu; mshift = 21; matchAll = 0; counts = g_counts1; }
    else { bins = NB2; dshift = 0; dmask = 0x3FFu; mshift = 10; matchAll = 0; counts = g_counts2; }

    int tid = threadIdx.x;
    for (int i = tid; i < 2 * bins; i += blockDim.x) sh[i] = 0u;
    __syncthreads();

    int b = blockIdx.y;
    unsigned p0 = g_prefix[b][0];
    unsigned p1 = g_prefix[b][1];
    const float* base = gt + (size_t)b * nper;

    for (int i = blockIdx.x * blockDim.x + tid; i < nper;
         i += gridDim.x * blockDim.x) {
        unsigned key = __float_as_uint(base[i]);
        unsigned d   = (key >> dshift) & dmask;
        unsigned hi  = key >> mshift;
        if (matchAll || hi == p0) atomicAdd(&sh[d], 1u);
        if (matchAll || hi == p1) atomicAdd(&sh[bins + d], 1u);
    }
    __syncthreads();

    unsigned* cbase = counts + (size_t)b * 2 * bins;
    for (int i = tid; i < 2 * bins; i += blockDim.x) {
        unsigned v = sh[i];
        if (v) atomicAdd(&cbase[i], v);
    }
}

// -------------------------------------------------------------------------
// Scan the counts, pick the digit containing the target rank, update state.
// One warp per (sample, rank); 8 warps = 256 threads, one block.
__global__ void radix_scan(int level, float frac) {
    int bins, shiftbits; const unsigned* counts;
    if (level == 0)      { bins = NB0; shiftbits = 11; counts = g_counts0; }
    else if (level == 1) { bins = NB1; shiftbits = 11; counts = g_counts1; }
    else                 { bins = NB2; shiftbits = 10; counts = g_counts2; }

    int warp = threadIdx.x >> 5;
    int lane = threadIdx.x & 31;
    if (warp < BATCH * 2) {
        int b = warp >> 1, r = warp & 1;
        const unsigned* cnt = counts + (size_t)(b * 2 + r) * bins;
        int cpl  = bins >> 5;           // counts per lane (64 or 32)
        int base = lane * cpl;
        unsigned chunk = 0;
        #pragma unroll 4
        for (int i = 0; i < cpl; i++) chunk += cnt[base + i];
        // inclusive warp scan
        unsigned incl = chunk;
        #pragma unroll
        for (int o = 1; o < 32; o <<= 1) {
            unsigned v = __shfl_up_sync(0xFFFFFFFFu, incl, o);
            if (lane >= o) incl += v;
        }
        unsigned excl = incl - chunk;
        unsigned rem  = g_rem[b][r];
        unsigned ball = __ballot_sync(0xFFFFFFFFu, (excl <= rem) && (rem < incl));
        int sel = __ffs(ball) - 1;
        if (lane == sel) {
            unsigned local = rem - excl;
            int d = base;
            for (;;) {
                unsigned c = cnt[d];
                if (local < c) break;
                local -= c;
                d++;
            }
            g_prefix[b][r] = (g_prefix[b][r] << shiftbits) | (unsigned)d;
            g_rem[b][r]    = local;
        }
    }
    if (level == 2) {
        __syncthreads();
        if (threadIdx.x < BATCH) {
            int b = threadIdx.x;
            float vlo = __uint_as_float(g_prefix[b][0]);  // sorted[k]
            float vhi = __uint_as_float(g_prefix[b][1]);  // sorted[k+1]
            float mv  = vlo + frac * (vhi - vlo);         // linear-interp quantile
            g_invbw[b] = (mv > 0.0f) ? (float)NBINS / mv : 0.0f;
        }
    }
}

// -------------------------------------------------------------------------
// Triangular soft histograms for pred and gt (2 bins touched per element).
__global__ void soft_hist(const float* __restrict__ pred,
                          const float* __restrict__ gt, int nper) {
    __shared__ float sh[2 * NBINS];
    int tid = threadIdx.x;
    if (tid < 2 * NBINS) sh[tid] = 0.0f;
    __syncthreads();

    int b = blockIdx.y;
    float invbw = g_invbw[b];
    const float* pb = pred + (size_t)b * nper;
    const float* gb = gt   + (size_t)b * nper;

    for (int i = blockIdx.x * blockDim.x + tid; i < nper;
         i += gridDim.x * blockDim.x) {
        float up = pb[i] * invbw;
        float ug = gb[i] * invbw;

        int   jp = (int)floorf(up);
        float fp = up - (float)jp;
        if (jp >= 0 && jp < NBINS) {
            atomicAdd(&sh[jp], 1.0f - fp);
            if (jp + 1 < NBINS) atomicAdd(&sh[jp + 1], fp);
        }
        int   jg = (int)floorf(ug);
        float fg = ug - (float)jg;
        if (jg >= 0 && jg < NBINS) {
            atomicAdd(&sh[NBINS + jg], 1.0f - fg);
            if (jg + 1 < NBINS) atomicAdd(&sh[NBINS + jg + 1], fg);
        }
    }
    __syncthreads();
    if (tid < 2 * NBINS) {
        float v = sh[tid];
        if (v != 0.0f) atomicAdd(&((float*)g_soft)[b * 2 * NBINS + tid], v);
    }
}

// -------------------------------------------------------------------------
__device__ __forceinline__ float block_sum64(float v, volatile float* red, int j) {
    red[j] = v;
    __syncthreads();
    #pragma unroll
    for (int s = 32; s >= 1; s >>= 1) {
        if (j < s) red[j] += red[j + s];
        __syncthreads();
    }
    float r = red[0];
    __syncthreads();
    return r;
}

__global__ void finalize(float* __restrict__ out) {
    __shared__ float red[NBINS];
    int j = threadIdx.x;   // 64 threads, one per bin
    float bw = expf(0.4f * (float)j / (float)NBINS);
    float total = 0.0f;
    #pragma unroll
    for (int b = 0; b < BATCH; b++) {
        float p = g_soft[b][0][j];
        float g = g_soft[b][1][j];
        float sp = block_sum64(p, red, j);
        float sg = block_sum64(g, red, j);
        float diff = fabsf(p / sp - g / sg) * bw;
        float s = block_sum64(diff, red, j);
        total += s * (1.0f / (float)NBINS);
    }
    if (j == 0) out[0] = total * (1.0f / (float)BATCH);
}

// -------------------------------------------------------------------------
extern "C" void kernel_launch(void* const* d_in, const int* in_sizes, int n_in,
                              void* d_out, int out_size) {
    const float* pred = (const float*)d_in[0];
    const float* gt   = (const float*)d_in[1];
    int ntot = in_sizes[0];
    int nper = ntot / BATCH;

    double pos = 0.95 * (double)(nper - 1);
    unsigned k = (unsigned)pos;
    float frac = (float)(pos - (double)k);

    dim3 grid(64, BATCH);
    init_kernel<<<64, 256>>>(k, k + 1);
    radix_hist<<<grid, 256>>>(gt, nper, 0);
    radix_scan<<<1, 256>>>(0, frac);
    radix_hist<<<grid, 256>>>(gt, nper, 1);
    radix_scan<<<1, 256>>>(1, frac);
    radix_hist<<<grid, 256>>>(gt, nper, 2);
    radix_scan<<<1, 256>>>(2, frac);
    soft_hist<<<grid, 256>>>(pred, gt, nper);
    finalize<<<1, NBINS>>>((float*)d_out);
}